// round 1
// baseline (speedup 1.0000x reference)
#include <cuda_runtime.h>
#include <cstdint>

// Problem dims
#define BB    256
#define NIN   64
#define DIN   128
#define MM    32
#define DOUTD 128
#define MD    (MM * DOUTD)          // 4096
#define VPB   (NIN * MD)            // 262144  (votes per b)
#define SCALE 0.08838834764831845f  // 1/sqrt(128)

// -------- device scratch (allocation-free: static device globals) ----------
__device__ float g_votes[(size_t)BB * NIN * MM * DOUTD];   // 268 MB
__device__ float g_ncv_a[(size_t)BB * MD];                 // 4 MB
__device__ float g_ncv_b[(size_t)BB * MD];                 // 4 MB

// -------- cp.async helpers -------------------------------------------------
__device__ __forceinline__ void cp_async16(void* smem_dst, const void* gmem_src) {
    unsigned s = (unsigned)__cvta_generic_to_shared(smem_dst);
    asm volatile("cp.async.cg.shared.global [%0], [%1], 16;\n" :: "r"(s), "l"(gmem_src));
}
__device__ __forceinline__ void cp_commit() {
    asm volatile("cp.async.commit_group;\n");
}
template <int N>
__device__ __forceinline__ void cp_wait() {
    asm volatile("cp.async.wait_group %0;\n" :: "n"(N));
}

// ===========================================================================
// K1: votes[b,n,m,d] = sum_a x[b,n,a] * W[n,a,m,d]
// Per n it is a GEMM: [B=256, K=128] x [K=128, N=4096].
// Block tile 64x64, full K resident in smem. fp32 FFMA.
// grid = (4096/64, 256/64, 64) = (64, 4, 64); 256 threads; 4x4 microtile.
// ===========================================================================
#define VOTES_SMEM ((DIN * 65 + DIN * 64) * 4)   // As[128][65] + Bs[128][64] = 66,048 B

__global__ __launch_bounds__(256) void votes_kernel(const float* __restrict__ x,
                                                    const float* __restrict__ W) {
    extern __shared__ float smem[];
    float* As = smem;                 // [DIN][65]  (k-major, padded, rows = b-local)
    float* Bs = smem + DIN * 65;      // [DIN][64]  (k-major, cols = m*128+d local)

    const int n   = blockIdx.z;
    const int b0  = blockIdx.y * 64;
    const int j0  = blockIdx.x * 64;
    const int tid = threadIdx.x;

    // ---- load A: x[b0+row][n][k]  ->  As[k][row] (conflict-free scalar stores)
    {
        const int k  = tid & 127;
        const int r0 = tid >> 7;  // 0 or 1
        const float* xp = x + (size_t)(b0 + r0) * (NIN * DIN) + (size_t)n * DIN + k;
        #pragma unroll
        for (int r = 0; r < 32; ++r) {
            As[(size_t)k * 65 + (r0 + r * 2)] = xp[(size_t)r * 2 * (NIN * DIN)];
        }
    }
    // ---- load B: W[n][k][j0+j] -> Bs[k][j] (float4)
    {
        const int j4  = (tid & 15) * 4;
        const int kk0 = tid >> 4;  // 0..15
        const float* wp = W + (size_t)n * (DIN * MD) + (size_t)kk0 * MD + j0 + j4;
        #pragma unroll
        for (int r = 0; r < 8; ++r) {
            float4 v = *(const float4*)(wp + (size_t)r * 16 * MD);
            *(float4*)&Bs[(size_t)(kk0 + r * 16) * 64 + j4] = v;
        }
    }
    __syncthreads();

    const int tx = tid & 15;   // col group (4 cols)
    const int ty = tid >> 4;   // row group (4 rows)

    float acc[4][4];
    #pragma unroll
    for (int i = 0; i < 4; ++i)
        #pragma unroll
        for (int j = 0; j < 4; ++j) acc[i][j] = 0.0f;

    #pragma unroll 8
    for (int k = 0; k < DIN; ++k) {
        float4 bv = *(const float4*)&Bs[(size_t)k * 64 + tx * 4];
        float a0 = As[(size_t)k * 65 + ty * 4 + 0];
        float a1 = As[(size_t)k * 65 + ty * 4 + 1];
        float a2 = As[(size_t)k * 65 + ty * 4 + 2];
        float a3 = As[(size_t)k * 65 + ty * 4 + 3];
        acc[0][0] += a0 * bv.x; acc[0][1] += a0 * bv.y; acc[0][2] += a0 * bv.z; acc[0][3] += a0 * bv.w;
        acc[1][0] += a1 * bv.x; acc[1][1] += a1 * bv.y; acc[1][2] += a1 * bv.z; acc[1][3] += a1 * bv.w;
        acc[2][0] += a2 * bv.x; acc[2][1] += a2 * bv.y; acc[2][2] += a2 * bv.z; acc[2][3] += a2 * bv.w;
        acc[3][0] += a3 * bv.x; acc[3][1] += a3 * bv.y; acc[3][2] += a3 * bv.z; acc[3][3] += a3 * bv.w;
    }

    float* vp = g_votes + (size_t)(b0 + ty * 4) * VPB + (size_t)n * MD + j0 + tx * 4;
    #pragma unroll
    for (int i = 0; i < 4; ++i) {
        float4 o; o.x = acc[i][0]; o.y = acc[i][1]; o.z = acc[i][2]; o.w = acc[i][3];
        *(float4*)(vp + (size_t)i * VPB) = o;
    }
}

// ===========================================================================
// K2: ncv0[b,m,d] = (1/M) * sum_n votes[b,n,m,d]
// ===========================================================================
__global__ __launch_bounds__(256) void ncv0_kernel() {
    const int idx = blockIdx.x * 256 + threadIdx.x;   // 0 .. 1048575
    const int b = idx >> 12;       // / 4096
    const int r = idx & 4095;
    const float* vp = g_votes + (size_t)b * VPB + r;
    float s = 0.0f;
    #pragma unroll
    for (int nn = 0; nn < NIN; ++nn) s += vp[(size_t)nn * MD];
    g_ncv_a[idx] = s * (1.0f / MM);
}

// ===========================================================================
// K3: one routing iteration. Block per b. votes streamed via cp.async
// double buffer. Computes logits -> softmax q -> ncv_new accumulation.
// phase 0: a->b ; phase 1: b->a ; phase 2 (final): a->out, also emits
// q and route_class_emb.
// ===========================================================================
#define ITER_SMEM ((MD + 2 * MD + 32) * 4)   // s_ncv + s_votes[2] + s_q = 49,280 B

__global__ __launch_bounds__(256) void route_iter_kernel(const float* __restrict__ act,
                                                         int phase,
                                                         float* __restrict__ out_ncv,
                                                         float* __restrict__ out_q,
                                                         float* __restrict__ out_route) {
    extern __shared__ float smem[];
    float* s_ncv   = smem;                  // [4096]
    float* s_votes = smem + MD;             // [2][4096]
    float* s_q     = smem + 3 * MD;         // [32] (doubles as logits staging)

    const int b   = blockIdx.x;
    const int tid = threadIdx.x;
    const int lane = tid & 31;
    const int warp = tid >> 5;
    const bool is_final = (phase == 2);

    const float* ncv_in = (phase == 1) ? g_ncv_b : g_ncv_a;
    float* ncv_out = is_final ? out_ncv : ((phase == 0) ? g_ncv_b : g_ncv_a);

    // load old ncv
    #pragma unroll
    for (int i = tid; i < MD; i += 256) s_ncv[i] = ncv_in[(size_t)b * MD + i];

    // register accumulator for new ncv: thread owns i = tid*4 + j*1024, j=0..3
    float4 acc4[4];
    #pragma unroll
    for (int j = 0; j < 4; ++j) { acc4[j].x = 0.f; acc4[j].y = 0.f; acc4[j].z = 0.f; acc4[j].w = 0.f; }

    const float* vbase = g_votes + (size_t)b * VPB;

    // prefetch n = 0
    #pragma unroll
    for (int i = tid * 4; i < MD; i += 1024) cp_async16(&s_votes[i], vbase + i);
    cp_commit();

    for (int n = 0; n < NIN; ++n) {
        const int buf = (n & 1) * MD;
        if (n + 1 < NIN) {
            const float* src = vbase + (size_t)(n + 1) * MD;
            const int nbuf = ((n + 1) & 1) * MD;
            #pragma unroll
            for (int i = tid * 4; i < MD; i += 1024) cp_async16(&s_votes[nbuf + i], src + i);
            cp_commit();
            cp_wait<1>();
        } else {
            cp_wait<0>();
        }
        __syncthreads();

        // ---- logits[m] = SCALE * sum_d votes[m,d] * ncv[m,d]; warp w -> m = 4w+j
        #pragma unroll
        for (int j = 0; j < 4; ++j) {
            const int m = warp * 4 + j;
            const float* vr = &s_votes[buf + m * DOUTD];
            const float* cr = &s_ncv[m * DOUTD];
            float p = vr[lane]       * cr[lane]
                    + vr[lane + 32]  * cr[lane + 32]
                    + vr[lane + 64]  * cr[lane + 64]
                    + vr[lane + 96]  * cr[lane + 96];
            p += __shfl_xor_sync(0xffffffffu, p, 16);
            p += __shfl_xor_sync(0xffffffffu, p, 8);
            p += __shfl_xor_sync(0xffffffffu, p, 4);
            p += __shfl_xor_sync(0xffffffffu, p, 2);
            p += __shfl_xor_sync(0xffffffffu, p, 1);
            if (lane == 0) s_q[m] = p;
        }
        __syncthreads();

        // ---- softmax over m (warp 0)
        if (warp == 0) {
            float v = s_q[lane] * SCALE;
            float mx = v;
            #pragma unroll
            for (int o = 16; o > 0; o >>= 1) mx = fmaxf(mx, __shfl_xor_sync(0xffffffffu, mx, o));
            float e = expf(v - mx);
            float sm = e;
            #pragma unroll
            for (int o = 16; o > 0; o >>= 1) sm += __shfl_xor_sync(0xffffffffu, sm, o);
            s_q[lane] = e / sm;
        }
        __syncthreads();

        // ---- accumulate ncv_new += q[m]*act*votes ; final: also emit route
        const float wa = act[b * NIN + n];
        #pragma unroll
        for (int j = 0; j < 4; ++j) {
            const int i = tid * 4 + j * 1024;
            const float qw = s_q[i >> 7] * wa;
            float4 v = *(const float4*)&s_votes[buf + i];
            v.x *= qw; v.y *= qw; v.z *= qw; v.w *= qw;
            acc4[j].x += v.x; acc4[j].y += v.y; acc4[j].z += v.z; acc4[j].w += v.w;
            if (is_final)
                *(float4*)(out_route + (size_t)b * VPB + (size_t)n * MD + i) = v;
        }
        if (is_final && tid < MM)
            out_q[(size_t)b * (NIN * MM) + n * MM + tid] = s_q[tid];
        __syncthreads();  // protect s_votes[buf] before next prefetch overwrites it
    }

    // write new ncv
    #pragma unroll
    for (int j = 0; j < 4; ++j) {
        const int i = tid * 4 + j * 1024;
        *(float4*)(ncv_out + (size_t)b * MD + i) = acc4[j];
    }
}

// ===========================================================================
// launch
// ===========================================================================
extern "C" void kernel_launch(void* const* d_in, const int* in_sizes, int n_in,
                              void* d_out, int out_size) {
    const float* x   = (const float*)d_in[0];
    const float* act = (const float*)d_in[1];
    const float* W   = (const float*)d_in[2];
    // d_in[3] = num_iter (always 3 for this problem; routing loop count fixed)

    float* out       = (float*)d_out;
    float* out_ncv   = out;                                          // [B, M, DOUT]
    float* out_q     = out + (size_t)BB * MM * DOUTD;                // [B, NIN, M]
    float* out_route = out_q + (size_t)BB * NIN * MM;                // [B, NIN, M, DOUT]

    cudaFuncSetAttribute(votes_kernel, cudaFuncAttributeMaxDynamicSharedMemorySize, VOTES_SMEM);
    cudaFuncSetAttribute(route_iter_kernel, cudaFuncAttributeMaxDynamicSharedMemorySize, ITER_SMEM);

    // K1: votes
    votes_kernel<<<dim3(MD / 64, BB / 64, NIN), 256, VOTES_SMEM>>>(x, W);
    // K2: ncv0
    ncv0_kernel<<<(BB * MD) / 256, 256>>>();
    // K3: three routing iterations (last one fused with output emission)
    route_iter_kernel<<<BB, 256, ITER_SMEM>>>(act, 0, nullptr, nullptr, nullptr);
    route_iter_kernel<<<BB, 256, ITER_SMEM>>>(act, 1, nullptr, nullptr, nullptr);
    route_iter_kernel<<<BB, 256, ITER_SMEM>>>(act, 2, out_ncv, out_q, out_route);
}

// round 9
// speedup vs baseline: 1.5529x; 1.5529x over previous
#include <cuda_runtime.h>
#include <cuda_bf16.h>
#include <cstdint>

// Problem dims
#define BB    256
#define NIN   64
#define DIN   128
#define MM    32
#define DOUTD 128
#define MD    (MM * DOUTD)          // 4096
#define VPB   (NIN * MD)            // 262144
#define SCALE 0.08838834764831845f  // 1/sqrt(128)
#define NCHUNK 4
#define NPC   (NIN / NCHUNK)        // 16

// -------- device scratch (allocation-free: static device globals) ----------
__device__ float g_votes[(size_t)BB * NIN * MM * DOUTD];     // 256 MiB
__device__ float g_ncv[(size_t)BB * MD];                     // 4 MiB
__device__ float g_part[(size_t)BB * NCHUNK * MD];           // 16 MiB

// -------- cp.async helpers -------------------------------------------------
__device__ __forceinline__ void cp_async16(void* smem_dst, const void* gmem_src) {
    unsigned s = (unsigned)__cvta_generic_to_shared(smem_dst);
    asm volatile("cp.async.cg.shared.global [%0], [%1], 16;\n" :: "r"(s), "l"(gmem_src));
}
__device__ __forceinline__ void cp_commit() { asm volatile("cp.async.commit_group;\n"); }
template <int N> __device__ __forceinline__ void cp_wait() {
    asm volatile("cp.async.wait_group %0;\n" :: "n"(N));
}

// -------- bf16 split helpers (all-scalar) ----------------------------------
__device__ __forceinline__ void split2(float a, float b, uint32_t& h, uint32_t& l) {
    __nv_bfloat16 ha = __float2bfloat16_rn(a);
    __nv_bfloat16 hb = __float2bfloat16_rn(b);
    float la = a - __bfloat162float(ha);
    float lb = b - __bfloat162float(hb);
    __nv_bfloat162 hp = __halves2bfloat162(ha, hb);
    __nv_bfloat162 lp = __halves2bfloat162(__float2bfloat16_rn(la), __float2bfloat16_rn(lb));
    h = *reinterpret_cast<uint32_t*>(&hp);
    l = *reinterpret_cast<uint32_t*>(&lp);
}
__device__ __forceinline__ uint32_t packbf(float k0, float k1, float& r0, float& r1) {
    __nv_bfloat16 h0 = __float2bfloat16_rn(k0);
    __nv_bfloat16 h1 = __float2bfloat16_rn(k1);
    r0 = k0 - __bfloat162float(h0);
    r1 = k1 - __bfloat162float(h1);
    __nv_bfloat162 p = __halves2bfloat162(h0, h1);
    return *reinterpret_cast<uint32_t*>(&p);
}
__device__ __forceinline__ uint32_t packbf2(float a, float b) {
    __nv_bfloat162 p = __halves2bfloat162(__float2bfloat16_rn(a), __float2bfloat16_rn(b));
    return *reinterpret_cast<uint32_t*>(&p);
}

#define MMA16816(c0, c1, c2, c3, a0, a1, a2, a3, b0, b1)                      \
    asm volatile(                                                             \
        "mma.sync.aligned.m16n8k16.row.col.f32.bf16.bf16.f32 "                \
        "{%0,%1,%2,%3}, {%4,%5,%6,%7}, {%8,%9}, {%0,%1,%2,%3};\n"             \
        : "+f"(c0), "+f"(c1), "+f"(c2), "+f"(c3)                              \
        : "r"(a0), "r"(a1), "r"(a2), "r"(a3), "r"(b0), "r"(b1))

// ===========================================================================
// K1: votes via split-bf16 tensor cores (all-scalar, zero arrays).
// Per n: GEMM [256 x 128] x [128 x 4096].
// Block tile 64(b) x 64(j), K=128 resident. 8 warps (4m x 2n), warp tile 16x32.
// grid = (MD/64, BB/64, NIN) = (64, 4, 64).
// ===========================================================================
#define BM   64
#define BN   64
#define LDK  136   // As pitch (bf16)
#define LDJW 72    // Bs pitch (u32 words, k-paired)
#define ASZ  (BM * LDK)
#define BSZ  (64 * LDJW)
#define VOTES_SMEM (2 * ASZ * 2 + 2 * BSZ * 4)   // 71,680 B

#define NT_BLOCK(C0, C1, C2, C3, JJ)                                          \
    {                                                                         \
        uint32_t bh0 = Bs_h[kp * LDJW + (JJ)];                                \
        uint32_t bh1 = Bs_h[(kp + 4) * LDJW + (JJ)];                          \
        uint32_t bl0 = Bs_l[kp * LDJW + (JJ)];                                \
        uint32_t bl1 = Bs_l[(kp + 4) * LDJW + (JJ)];                          \
        MMA16816(C0, C1, C2, C3, ah0, ah1, ah2, ah3, bh0, bh1);               \
        MMA16816(C0, C1, C2, C3, ah0, ah1, ah2, ah3, bl0, bl1);               \
        MMA16816(C0, C1, C2, C3, al0, al1, al2, al3, bh0, bh1);               \
    }

__global__ __launch_bounds__(256) void votes_tc_kernel(const float* __restrict__ x,
                                                       const float* __restrict__ W) {
    extern __shared__ char sm_[];
    __nv_bfloat16* As_h = (__nv_bfloat16*)sm_;
    __nv_bfloat16* As_l = As_h + ASZ;
    uint32_t* Bs_h = (uint32_t*)(As_l + ASZ);
    uint32_t* Bs_l = Bs_h + BSZ;
    float* stage = (float*)sm_;   // epilogue reuse: [64][68] = 17,408 B

    const int n  = blockIdx.z;
    const int b0 = blockIdx.y * BM;
    const int j0 = blockIdx.x * BN;
    const int tid  = threadIdx.x;
    const int lane = tid & 31;
    const int warp = tid >> 5;
    const int warp_m = warp >> 1;   // 0..3 (16 rows each)
    const int warp_n = warp & 1;    // 0..1 (32 cols each)

    // ---- load + split A: x[b0+r][n][k]
    {
        const float* xb = x + (size_t)b0 * (NIN * DIN) + (size_t)n * DIN;
        #pragma unroll
        for (int i = 0; i < 8; ++i) {
            int idx = tid + i * 256;
            int r = idx >> 5, c4 = idx & 31;
            float4 v = *(const float4*)(xb + (size_t)r * (NIN * DIN) + c4 * 4);
            uint32_t h01, l01, h23, l23;
            split2(v.x, v.y, h01, l01);
            split2(v.z, v.w, h23, l23);
            uint32_t* ph = (uint32_t*)(As_h + r * LDK + c4 * 4);
            uint32_t* pl = (uint32_t*)(As_l + r * LDK + c4 * 4);
            ph[0] = h01; ph[1] = h23;
            pl[0] = l01; pl[1] = l23;
        }
    }
    // ---- load + split B (k-paired): Bs[kp][j] u32 = {k=2kp, k=2kp+1}
    {
        const float* wb = W + (size_t)n * (DIN * MD) + j0;
        #pragma unroll
        for (int i = 0; i < 4; ++i) {
            int idx = tid + i * 256;
            int kp = idx >> 4, c4 = idx & 15;
            const float* w0 = wb + (size_t)(2 * kp) * MD + c4 * 4;
            float4 u = *(const float4*)w0;          // k even
            float4 v = *(const float4*)(w0 + MD);   // k odd
            float lu0, lv0, lu1, lv1, lu2, lv2, lu3, lv3;
            uint32_t Hx = packbf(u.x, v.x, lu0, lv0);
            uint32_t Hy = packbf(u.y, v.y, lu1, lv1);
            uint32_t Hz = packbf(u.z, v.z, lu2, lv2);
            uint32_t Hw = packbf(u.w, v.w, lu3, lv3);
            uint32_t Lx = packbf2(lu0, lv0);
            uint32_t Ly = packbf2(lu1, lv1);
            uint32_t Lz = packbf2(lu2, lv2);
            uint32_t Lw = packbf2(lu3, lv3);
            *(uint4*)&Bs_h[kp * LDJW + c4 * 4] = make_uint4(Hx, Hy, Hz, Hw);
            *(uint4*)&Bs_l[kp * LDJW + c4 * 4] = make_uint4(Lx, Ly, Lz, Lw);
        }
    }
    __syncthreads();

    float c0_0 = 0.f, c0_1 = 0.f, c0_2 = 0.f, c0_3 = 0.f;
    float c1_0 = 0.f, c1_1 = 0.f, c1_2 = 0.f, c1_3 = 0.f;
    float c2_0 = 0.f, c2_1 = 0.f, c2_2 = 0.f, c2_3 = 0.f;
    float c3_0 = 0.f, c3_1 = 0.f, c3_2 = 0.f, c3_3 = 0.f;

    const int arow = warp_m * 16 + (lane >> 2);
    const int jcol = warp_n * 32 + (lane >> 2);

    #pragma unroll
    for (int ks = 0; ks < 8; ++ks) {
        const int kk = ks * 16 + 2 * (lane & 3);
        const __nv_bfloat16* pa = As_h + arow * LDK + kk;
        const __nv_bfloat16* qa = As_l + arow * LDK + kk;
        uint32_t ah0 = *(const uint32_t*)pa;
        uint32_t ah1 = *(const uint32_t*)(pa + 8 * LDK);
        uint32_t ah2 = *(const uint32_t*)(pa + 8);
        uint32_t ah3 = *(const uint32_t*)(pa + 8 * LDK + 8);
        uint32_t al0 = *(const uint32_t*)qa;
        uint32_t al1 = *(const uint32_t*)(qa + 8 * LDK);
        uint32_t al2 = *(const uint32_t*)(qa + 8);
        uint32_t al3 = *(const uint32_t*)(qa + 8 * LDK + 8);
        const int kp = ks * 8 + (lane & 3);
        NT_BLOCK(c0_0, c0_1, c0_2, c0_3, jcol);
        NT_BLOCK(c1_0, c1_1, c1_2, c1_3, jcol + 8);
        NT_BLOCK(c2_0, c2_1, c2_2, c2_3, jcol + 16);
        NT_BLOCK(c3_0, c3_1, c3_2, c3_3, jcol + 24);
    }
    __syncthreads();   // done with As/Bs; reuse for staging

    // ---- stage accumulators to smem [64][68]
    {
        const int row = warp_m * 16 + (lane >> 2);
        const int cb  = warp_n * 32 + 2 * (lane & 3);
        *(float2*)&stage[row * 68 + cb]            = make_float2(c0_0, c0_1);
        *(float2*)&stage[(row + 8) * 68 + cb]      = make_float2(c0_2, c0_3);
        *(float2*)&stage[row * 68 + cb + 8]        = make_float2(c1_0, c1_1);
        *(float2*)&stage[(row + 8) * 68 + cb + 8]  = make_float2(c1_2, c1_3);
        *(float2*)&stage[row * 68 + cb + 16]       = make_float2(c2_0, c2_1);
        *(float2*)&stage[(row + 8) * 68 + cb + 16] = make_float2(c2_2, c2_3);
        *(float2*)&stage[row * 68 + cb + 24]       = make_float2(c3_0, c3_1);
        *(float2*)&stage[(row + 8) * 68 + cb + 24] = make_float2(c3_2, c3_3);
    }
    __syncthreads();

    // ---- coalesced write to gmem
    float* vout = g_votes + (size_t)b0 * VPB + (size_t)n * MD + j0;
    #pragma unroll
    for (int i = 0; i < 4; ++i) {
        int idx = tid + i * 256;
        int r = idx >> 4, c4 = idx & 15;
        float4 o = *(float4*)&stage[r * 68 + c4 * 4];
        *(float4*)(vout + (size_t)r * VPB + c4 * 4) = o;
    }
}

// ===========================================================================
// K2: ncv0[b,j] = (1/M) * sum_n votes[b,n,j]   (float4, bounded unroll)
// ===========================================================================
__global__ __launch_bounds__(256) void ncv0_kernel() {
    const int idx = blockIdx.x * 256 + threadIdx.x;   // 0 .. 262143
    const int b  = idx >> 10;
    const int r4 = (idx & 1023) * 4;
    const float* vp = g_votes + (size_t)b * VPB + r4;
    float4 s = make_float4(0.f, 0.f, 0.f, 0.f);
    #pragma unroll 4
    for (int nn = 0; nn < NIN; ++nn) {
        float4 v = *(const float4*)(vp + (size_t)nn * MD);
        s.x += v.x; s.y += v.y; s.z += v.z; s.w += v.w;
    }
    s.x *= (1.0f / MM); s.y *= (1.0f / MM); s.z *= (1.0f / MM); s.w *= (1.0f / MM);
    *(float4*)(g_ncv + (size_t)b * MD + r4) = s;
}

// ===========================================================================
// K3: routing iteration, n-chunked. grid (BB, NCHUNK); each block: 16 n's.
// ===========================================================================
#define ITER_SMEM ((MD + 2 * MD + 32) * 4)   // 49,280 B

__global__ __launch_bounds__(256) void route_iter_kernel(const float* __restrict__ act,
                                                         int is_final,
                                                         float* __restrict__ out_q,
                                                         float* __restrict__ out_route) {
    extern __shared__ float smem[];
    float* s_ncv   = smem;                  // [4096]
    float* s_votes = smem + MD;             // [2][4096]
    float* s_q     = smem + 3 * MD;         // [32]

    const int b     = blockIdx.x;
    const int chunk = blockIdx.y;
    const int n0    = chunk * NPC;
    const int tid  = threadIdx.x;
    const int lane = tid & 31;
    const int warp = tid >> 5;

    #pragma unroll 4
    for (int i = tid; i < MD; i += 256) s_ncv[i] = g_ncv[(size_t)b * MD + i];

    float4 acc0 = make_float4(0.f, 0.f, 0.f, 0.f);
    float4 acc1 = make_float4(0.f, 0.f, 0.f, 0.f);
    float4 acc2 = make_float4(0.f, 0.f, 0.f, 0.f);
    float4 acc3 = make_float4(0.f, 0.f, 0.f, 0.f);

    const float* vbase = g_votes + (size_t)b * VPB + (size_t)n0 * MD;

    #pragma unroll
    for (int i = tid * 4; i < MD; i += 1024) cp_async16(&s_votes[i], vbase + i);
    cp_commit();

    for (int nn = 0; nn < NPC; ++nn) {
        const int n = n0 + nn;
        const int buf = (nn & 1) * MD;
        if (nn + 1 < NPC) {
            const float* src = vbase + (size_t)(nn + 1) * MD;
            const int nbuf = ((nn + 1) & 1) * MD;
            #pragma unroll
            for (int i = tid * 4; i < MD; i += 1024) cp_async16(&s_votes[nbuf + i], src + i);
            cp_commit();
            cp_wait<1>();
        } else {
            cp_wait<0>();
        }
        __syncthreads();

        // logits[m]: warp w handles m = 4w..4w+3
        #pragma unroll
        for (int j = 0; j < 4; ++j) {
            const int m = warp * 4 + j;
            const float* vr = &s_votes[buf + m * DOUTD];
            const float* cr = &s_ncv[m * DOUTD];
            float p = vr[lane]      * cr[lane]
                    + vr[lane + 32] * cr[lane + 32]
                    + vr[lane + 64] * cr[lane + 64]
                    + vr[lane + 96] * cr[lane + 96];
            p += __shfl_xor_sync(0xffffffffu, p, 16);
            p += __shfl_xor_sync(0xffffffffu, p, 8);
            p += __shfl_xor_sync(0xffffffffu, p, 4);
            p += __shfl_xor_sync(0xffffffffu, p, 2);
            p += __shfl_xor_sync(0xffffffffu, p, 1);
            if (lane == 0) s_q[m] = p;
        }
        __syncthreads();

        if (warp == 0) {
            float v = s_q[lane] * SCALE;
            float mx = v;
            #pragma unroll
            for (int o = 16; o > 0; o >>= 1) mx = fmaxf(mx, __shfl_xor_sync(0xffffffffu, mx, o));
            float e = expf(v - mx);
            float sm = e;
            #pragma unroll
            for (int o = 16; o > 0; o >>= 1) sm += __shfl_xor_sync(0xffffffffu, sm, o);
            s_q[lane] = e / sm;
        }
        __syncthreads();

        const float wa = act[b * NIN + n];
        {
            const int i0 = tid * 4;
            float q0 = s_q[i0 >> 7] * wa;
            float q1 = s_q[(i0 + 1024) >> 7] * wa;
            float q2 = s_q[(i0 + 2048) >> 7] * wa;
            float q3 = s_q[(i0 + 3072) >> 7] * wa;
            float4 v0 = *(const float4*)&s_votes[buf + i0];
            float4 v1 = *(const float4*)&s_votes[buf + i0 + 1024];
            float4 v2 = *(const float4*)&s_votes[buf + i0 + 2048];
            float4 v3 = *(const float4*)&s_votes[buf + i0 + 3072];
            v0.x *= q0; v0.y *= q0; v0.z *= q0; v0.w *= q0;
            v1.x *= q1; v1.y *= q1; v1.z *= q1; v1.w *= q1;
            v2.x *= q2; v2.y *= q2; v2.z *= q2; v2.w *= q2;
            v3.x *= q3; v3.y *= q3; v3.z *= q3; v3.w *= q3;
            acc0.x += v0.x; acc0.y += v0.y; acc0.z += v0.z; acc0.w += v0.w;
            acc1.x += v1.x; acc1.y += v1.y; acc1.z += v1.z; acc1.w += v1.w;
            acc2.x += v2.x; acc2.y += v2.y; acc2.z += v2.z; acc2.w += v2.w;
            acc3.x += v3.x; acc3.y += v3.y; acc3.z += v3.z; acc3.w += v3.w;
            if (is_final) {
                float* rp = out_route + (size_t)b * VPB + (size_t)n * MD;
                *(float4*)(rp + i0)        = v0;
                *(float4*)(rp + i0 + 1024) = v1;
                *(float4*)(rp + i0 + 2048) = v2;
                *(float4*)(rp + i0 + 3072) = v3;
            }
        }
        if (is_final && tid < MM)
            out_q[(size_t)b * (NIN * MM) + n * MM + tid] = s_q[tid];
        __syncthreads();
    }

    float* pp = g_part + ((size_t)b * NCHUNK + chunk) * MD;
    const int i0 = tid * 4;
    *(float4*)(pp + i0)        = acc0;
    *(float4*)(pp + i0 + 1024) = acc1;
    *(float4*)(pp + i0 + 2048) = acc2;
    *(float4*)(pp + i0 + 3072) = acc3;
}

// ===========================================================================
// K4: reduce partials -> g_ncv (to_out=0) or out_ncv (to_out=1).
// FIX: g_ncv is selected INSIDE device code. Passing the __device__ symbol
// from host code (previous rounds) handed the kernel a host shadow address;
// via ATS/HMM it "worked" but triggered a fixed 128 MiB driver fault pool ->
// the allocation-guard failure in rounds 2-8.
// ===========================================================================
__global__ __launch_bounds__(256) void reduce_kernel(int to_out, float* __restrict__ out_ncv) {
    float* dst = to_out ? out_ncv : g_ncv;   // device-side symbol reference: valid
    const int idx = blockIdx.x * 256 + threadIdx.x;  // 0 .. 262143
    const int b  = idx >> 10;
    const int r4 = (idx & 1023) * 4;
    const float* pp = g_part + (size_t)b * NCHUNK * MD + r4;
    float4 s = make_float4(0.f, 0.f, 0.f, 0.f);
    #pragma unroll 4
    for (int c = 0; c < NCHUNK; ++c) {
        float4 v = *(const float4*)(pp + (size_t)c * MD);
        s.x += v.x; s.y += v.y; s.z += v.z; s.w += v.w;
    }
    *(float4*)(dst + (size_t)b * MD + r4) = s;
}

// ===========================================================================
// launch
// ===========================================================================
extern "C" void kernel_launch(void* const* d_in, const int* in_sizes, int n_in,
                              void* d_out, int out_size) {
    const float* x   = (const float*)d_in[0];
    const float* act = (const float*)d_in[1];
    const float* W   = (const float*)d_in[2];

    float* out       = (float*)d_out;
    float* out_ncv   = out;
    float* out_q     = out + (size_t)BB * MM * DOUTD;
    float* out_route = out_q + (size_t)BB * NIN * MM;

    cudaFuncSetAttribute(votes_tc_kernel, cudaFuncAttributeMaxDynamicSharedMemorySize, VOTES_SMEM);
    cudaFuncSetAttribute(route_iter_kernel, cudaFuncAttributeMaxDynamicSharedMemorySize, ITER_SMEM);

    votes_tc_kernel<<<dim3(MD / BN, BB / BM, NIN), 256, VOTES_SMEM>>>(x, W);
    ncv0_kernel<<<(BB * MD / 4) / 256, 256>>>();

    route_iter_kernel<<<dim3(BB, NCHUNK), 256, ITER_SMEM>>>(act, 0, nullptr, nullptr);
    reduce_kernel<<<(BB * MD / 4) / 256, 256>>>(0, nullptr);
    route_iter_kernel<<<dim3(BB, NCHUNK), 256, ITER_SMEM>>>(act, 0, nullptr, nullptr);
    reduce_kernel<<<(BB * MD / 4) / 256, 256>>>(0, nullptr);
    route_iter_kernel<<<dim3(BB, NCHUNK), 256, ITER_SMEM>>>(act, 1, out_q, out_route);
    reduce_kernel<<<(BB * MD / 4) / 256, 256>>>(1, out_ncv);
}

// round 10
// speedup vs baseline: 1.6292x; 1.0491x over previous
#include <cuda_runtime.h>
#include <cuda_bf16.h>
#include <cstdint>

// Problem dims
#define BB    256
#define NIN   64
#define DIN   128
#define MM    32
#define DOUTD 128
#define MD    (MM * DOUTD)          // 4096
#define VPB   (NIN * MD)            // 262144
#define SCALE 0.08838834764831845f  // 1/sqrt(128)
#define NCHUNK 4
#define NPC   (NIN / NCHUNK)        // 16

// -------- device scratch ---------------------------------------------------
__device__ float g_votes[(size_t)BB * NIN * MM * DOUTD];     // 256 MiB
__device__ float g_ncv[(size_t)BB * MD];                     // 4 MiB
__device__ float g_part[(size_t)BB * NCHUNK * MD];           // 16 MiB
__device__ float g_wt[(size_t)NIN * DIN * MD];               // 128 MiB (tf32-rounded W)
__device__ float g_xt[(size_t)BB * NIN * DIN];               // 8 MiB  (tf32-rounded x)

// -------- helpers ------------------------------------------------------------
__device__ __forceinline__ void cp_async16(void* smem_dst, const void* gmem_src) {
    unsigned s = (unsigned)__cvta_generic_to_shared(smem_dst);
    asm volatile("cp.async.cg.shared.global [%0], [%1], 16;\n" :: "r"(s), "l"(gmem_src));
}
__device__ __forceinline__ void cp_commit() { asm volatile("cp.async.commit_group;\n"); }
template <int N> __device__ __forceinline__ void cp_wait() {
    asm volatile("cp.async.wait_group %0;\n" :: "n"(N));
}
__device__ __forceinline__ float cvt_tf32(float f) {
    uint32_t o;
    asm("cvt.rna.tf32.f32 %0, %1;" : "=r"(o) : "f"(f));
    return __uint_as_float(o);
}
__device__ __forceinline__ uint32_t fbits(float f) { return __float_as_uint(f); }

#define MMA_TF32(c0, c1, c2, c3, a0, a1, a2, a3, b0, b1)                       \
    asm volatile(                                                              \
        "mma.sync.aligned.m16n8k8.row.col.f32.tf32.tf32.f32 "                  \
        "{%0,%1,%2,%3}, {%4,%5,%6,%7}, {%8,%9}, {%0,%1,%2,%3};\n"              \
        : "+f"(c0), "+f"(c1), "+f"(c2), "+f"(c3)                               \
        : "r"(a0), "r"(a1), "r"(a2), "r"(a3), "r"(b0), "r"(b1))

// ===========================================================================
// K0: round W and x to tf32 (rna). Pure streaming, float4.
// ===========================================================================
#define WF4 ((NIN * DIN * MD) / 4)        // 8,388,608
#define XF4 ((BB * NIN * DIN) / 4)        // 524,288
#define PREP_BLOCKS ((WF4 + XF4) / 256)   // 34,816

__global__ __launch_bounds__(256) void prep_kernel(const float* __restrict__ x,
                                                   const float* __restrict__ W) {
    const int idx = blockIdx.x * 256 + threadIdx.x;
    if (idx < WF4) {
        float4 v = ((const float4*)W)[idx];
        v.x = cvt_tf32(v.x); v.y = cvt_tf32(v.y); v.z = cvt_tf32(v.z); v.w = cvt_tf32(v.w);
        ((float4*)g_wt)[idx] = v;
    } else {
        const int i2 = idx - WF4;
        float4 v = ((const float4*)x)[i2];
        v.x = cvt_tf32(v.x); v.y = cvt_tf32(v.y); v.z = cvt_tf32(v.z); v.w = cvt_tf32(v.w);
        ((float4*)g_xt)[i2] = v;
    }
}

// ===========================================================================
// K1: votes via tf32 tensor cores, n-loop with fused ncv0.
// Block tile 128(b) x 64(j), loops all 64 n with double-buffered cp.async.
// grid = (MD/64, BB/128) = (64, 2) = 128 blocks (one wave).
// 8 warps (4m x 2n), warp tile 32x32, 32 fp32 accumulators/thread + 32 ncv.
// ===========================================================================
#define BMV 128
#define BNV 64
#define APITCH 132                        // floats; bank-conflict-free frag loads
#define BPITCH 72
#define ABYTES (BMV * APITCH * 4)         // 67,584
#define BBYTES (DIN * BPITCH * 4)         // 36,864
#define VSMEM  (2 * (ABYTES + BBYTES))    // 208,896 B

__global__ __launch_bounds__(256) void votes_tf32_kernel() {
    extern __shared__ float sm_[];
    // layout: [A0][B0][A1][B1]
    float* Abuf0 = sm_;
    float* Bbuf0 = sm_ + BMV * APITCH;
    float* Abuf1 = Bbuf0 + DIN * BPITCH;
    float* Bbuf1 = Abuf1 + BMV * APITCH;

    const int j0 = blockIdx.x * BNV;
    const int b0 = blockIdx.y * BMV;
    const int tid  = threadIdx.x;
    const int lane = tid & 31;
    const int warp = tid >> 5;
    const int warp_m = warp >> 1;    // 0..3 (32 rows each)
    const int warp_n = warp & 1;     // 0..1 (32 cols each)
    const int g = lane >> 2;         // group id 0..7
    const int t = lane & 3;          // thread-in-group 0..3

    // cp.async assignments (per thread):
    // A: 16 chunks: id = tid + i*256; row = id>>5 (0..127), c = id&31 (16B chunks)
    // B:  8 chunks: id = tid + i*256; k   = id>>4 (0..127), c = id&15
    const float* xbase = g_xt + (size_t)b0 * (NIN * DIN);
    const float* wbase = g_wt + j0;

    auto issue_tile = [&](float* Ad, float* Bd, int n) {
        const float* xs = xbase + n * DIN;
        #pragma unroll
        for (int i = 0; i < 16; ++i) {
            int id = tid + i * 256;
            int row = id >> 5, c = id & 31;
            cp_async16(Ad + row * APITCH + c * 4, xs + (size_t)row * (NIN * DIN) + c * 4);
        }
        const float* ws = wbase + (size_t)n * (DIN * MD);
        #pragma unroll
        for (int i = 0; i < 8; ++i) {
            int id = tid + i * 256;
            int k = id >> 4, c = id & 15;
            cp_async16(Bd + k * BPITCH + c * 4, ws + (size_t)k * MD + c * 4);
        }
        cp_commit();
    };

    float c[2][4][4];
    float ncv[2][4][4];
    #pragma unroll
    for (int mt = 0; mt < 2; ++mt)
        #pragma unroll
        for (int nt = 0; nt < 4; ++nt)
            #pragma unroll
            for (int q = 0; q < 4; ++q) { c[mt][nt][q] = 0.f; ncv[mt][nt][q] = 0.f; }

    issue_tile(Abuf0, Bbuf0, 0);

    for (int n = 0; n < NIN; ++n) {
        float* Ab = (n & 1) ? Abuf1 : Abuf0;
        float* Bb = (n & 1) ? Bbuf1 : Bbuf0;
        if (n + 1 < NIN) {
            issue_tile((n & 1) ? Abuf0 : Abuf1, (n & 1) ? Bbuf0 : Bbuf1, n + 1);
            cp_wait<1>();
        } else {
            cp_wait<0>();
        }
        __syncthreads();

        // ---- mainloop: 16 k-steps of 8
        #pragma unroll
        for (int ks = 0; ks < 16; ++ks) {
            const int kb = ks * 8;
            uint32_t a[2][4];
            #pragma unroll
            for (int mt = 0; mt < 2; ++mt) {
                const float* ap = Ab + (warp_m * 32 + mt * 16 + g) * APITCH + kb + t;
                a[mt][0] = fbits(ap[0]);
                a[mt][1] = fbits(ap[8 * APITCH]);
                a[mt][2] = fbits(ap[4]);
                a[mt][3] = fbits(ap[8 * APITCH + 4]);
            }
            #pragma unroll
            for (int nt = 0; nt < 4; ++nt) {
                const int j = warp_n * 32 + nt * 8 + g;
                const float* bp = Bb + (kb + t) * BPITCH + j;
                uint32_t bb0 = fbits(bp[0]);
                uint32_t bb1 = fbits(bp[4 * BPITCH]);
                #pragma unroll
                for (int mt = 0; mt < 2; ++mt) {
                    MMA_TF32(c[mt][nt][0], c[mt][nt][1], c[mt][nt][2], c[mt][nt][3],
                             a[mt][0], a[mt][1], a[mt][2], a[mt][3], bb0, bb1);
                }
            }
        }

        // ---- epilogue: write votes tile, accumulate ncv, reset c
        #pragma unroll
        for (int mt = 0; mt < 2; ++mt) {
            const int row = warp_m * 32 + mt * 16 + g;
            float* vp = g_votes + (size_t)(b0 + row) * VPB + (size_t)n * MD + j0;
            #pragma unroll
            for (int nt = 0; nt < 4; ++nt) {
                const int col = warp_n * 32 + nt * 8 + 2 * t;
                *(float2*)(vp + col)           = make_float2(c[mt][nt][0], c[mt][nt][1]);
                *(float2*)(vp + 8 * VPB + col) = make_float2(c[mt][nt][2], c[mt][nt][3]);
                ncv[mt][nt][0] += c[mt][nt][0]; c[mt][nt][0] = 0.f;
                ncv[mt][nt][1] += c[mt][nt][1]; c[mt][nt][1] = 0.f;
                ncv[mt][nt][2] += c[mt][nt][2]; c[mt][nt][2] = 0.f;
                ncv[mt][nt][3] += c[mt][nt][3]; c[mt][nt][3] = 0.f;
            }
        }
        __syncthreads();   // protect smem buffers before next prefetch overwrite
    }

    // ---- write ncv0 = (1/M) * sum_n votes  (fused!)
    #pragma unroll
    for (int mt = 0; mt < 2; ++mt) {
        const int row = warp_m * 32 + mt * 16 + g;
        float* np = g_ncv + (size_t)(b0 + row) * MD + j0;
        #pragma unroll
        for (int nt = 0; nt < 4; ++nt) {
            const int col = warp_n * 32 + nt * 8 + 2 * t;
            *(float2*)(np + col) =
                make_float2(ncv[mt][nt][0] * (1.0f / MM), ncv[mt][nt][1] * (1.0f / MM));
            *(float2*)(np + 8 * MD + col) =
                make_float2(ncv[mt][nt][2] * (1.0f / MM), ncv[mt][nt][3] * (1.0f / MM));
        }
    }
}

// ===========================================================================
// K3: routing iteration, n-chunked. grid (BB, NCHUNK). (Unchanged — passed R9.)
// ===========================================================================
#define ITER_SMEM ((MD + 2 * MD + 32) * 4)   // 49,280 B

__global__ __launch_bounds__(256) void route_iter_kernel(const float* __restrict__ act,
                                                         int is_final,
                                                         float* __restrict__ out_q,
                                                         float* __restrict__ out_route) {
    extern __shared__ float smem[];
    float* s_ncv   = smem;                  // [4096]
    float* s_votes = smem + MD;             // [2][4096]
    float* s_q     = smem + 3 * MD;         // [32]

    const int b     = blockIdx.x;
    const int chunk = blockIdx.y;
    const int n0    = chunk * NPC;
    const int tid  = threadIdx.x;
    const int lane = tid & 31;
    const int warp = tid >> 5;

    #pragma unroll 4
    for (int i = tid; i < MD; i += 256) s_ncv[i] = g_ncv[(size_t)b * MD + i];

    float4 acc0 = make_float4(0.f, 0.f, 0.f, 0.f);
    float4 acc1 = make_float4(0.f, 0.f, 0.f, 0.f);
    float4 acc2 = make_float4(0.f, 0.f, 0.f, 0.f);
    float4 acc3 = make_float4(0.f, 0.f, 0.f, 0.f);

    const float* vbase = g_votes + (size_t)b * VPB + (size_t)n0 * MD;

    #pragma unroll
    for (int i = tid * 4; i < MD; i += 1024) cp_async16(&s_votes[i], vbase + i);
    cp_commit();

    for (int nn = 0; nn < NPC; ++nn) {
        const int n = n0 + nn;
        const int buf = (nn & 1) * MD;
        if (nn + 1 < NPC) {
            const float* src = vbase + (size_t)(nn + 1) * MD;
            const int nbuf = ((nn + 1) & 1) * MD;
            #pragma unroll
            for (int i = tid * 4; i < MD; i += 1024) cp_async16(&s_votes[nbuf + i], src + i);
            cp_commit();
            cp_wait<1>();
        } else {
            cp_wait<0>();
        }
        __syncthreads();

        #pragma unroll
        for (int j = 0; j < 4; ++j) {
            const int m = warp * 4 + j;
            const float* vr = &s_votes[buf + m * DOUTD];
            const float* cr = &s_ncv[m * DOUTD];
            float p = vr[lane]      * cr[lane]
                    + vr[lane + 32] * cr[lane + 32]
                    + vr[lane + 64] * cr[lane + 64]
                    + vr[lane + 96] * cr[lane + 96];
            p += __shfl_xor_sync(0xffffffffu, p, 16);
            p += __shfl_xor_sync(0xffffffffu, p, 8);
            p += __shfl_xor_sync(0xffffffffu, p, 4);
            p += __shfl_xor_sync(0xffffffffu, p, 2);
            p += __shfl_xor_sync(0xffffffffu, p, 1);
            if (lane == 0) s_q[m] = p;
        }
        __syncthreads();

        if (warp == 0) {
            float v = s_q[lane] * SCALE;
            float mx = v;
            #pragma unroll
            for (int o = 16; o > 0; o >>= 1) mx = fmaxf(mx, __shfl_xor_sync(0xffffffffu, mx, o));
            float e = expf(v - mx);
            float sm = e;
            #pragma unroll
            for (int o = 16; o > 0; o >>= 1) sm += __shfl_xor_sync(0xffffffffu, sm, o);
            s_q[lane] = e / sm;
        }
        __syncthreads();

        const float wa = act[b * NIN + n];
        {
            const int i0 = tid * 4;
            float q0 = s_q[i0 >> 7] * wa;
            float q1 = s_q[(i0 + 1024) >> 7] * wa;
            float q2 = s_q[(i0 + 2048) >> 7] * wa;
            float q3 = s_q[(i0 + 3072) >> 7] * wa;
            float4 v0 = *(const float4*)&s_votes[buf + i0];
            float4 v1 = *(const float4*)&s_votes[buf + i0 + 1024];
            float4 v2 = *(const float4*)&s_votes[buf + i0 + 2048];
            float4 v3 = *(const float4*)&s_votes[buf + i0 + 3072];
            v0.x *= q0; v0.y *= q0; v0.z *= q0; v0.w *= q0;
            v1.x *= q1; v1.y *= q1; v1.z *= q1; v1.w *= q1;
            v2.x *= q2; v2.y *= q2; v2.z *= q2; v2.w *= q2;
            v3.x *= q3; v3.y *= q3; v3.z *= q3; v3.w *= q3;
            acc0.x += v0.x; acc0.y += v0.y; acc0.z += v0.z; acc0.w += v0.w;
            acc1.x += v1.x; acc1.y += v1.y; acc1.z += v1.z; acc1.w += v1.w;
            acc2.x += v2.x; acc2.y += v2.y; acc2.z += v2.z; acc2.w += v2.w;
            acc3.x += v3.x; acc3.y += v3.y; acc3.z += v3.z; acc3.w += v3.w;
            if (is_final) {
                float* rp = out_route + (size_t)b * VPB + (size_t)n * MD;
                *(float4*)(rp + i0)        = v0;
                *(float4*)(rp + i0 + 1024) = v1;
                *(float4*)(rp + i0 + 2048) = v2;
                *(float4*)(rp + i0 + 3072) = v3;
            }
        }
        if (is_final && tid < MM)
            out_q[(size_t)b * (NIN * MM) + n * MM + tid] = s_q[tid];
        __syncthreads();
    }

    float* pp = g_part + ((size_t)b * NCHUNK + chunk) * MD;
    const int i0 = tid * 4;
    *(float4*)(pp + i0)        = acc0;
    *(float4*)(pp + i0 + 1024) = acc1;
    *(float4*)(pp + i0 + 2048) = acc2;
    *(float4*)(pp + i0 + 3072) = acc3;
}

// ===========================================================================
// K4: reduce partials -> g_ncv (to_out=0) or out_ncv (to_out=1).
// g_ncv selected INSIDE device code (host-side __device__ symbol = R2-8 bug).
// ===========================================================================
__global__ __launch_bounds__(256) void reduce_kernel(int to_out, float* __restrict__ out_ncv) {
    float* dst = to_out ? out_ncv : g_ncv;
    const int idx = blockIdx.x * 256 + threadIdx.x;
    const int b  = idx >> 10;
    const int r4 = (idx & 1023) * 4;
    const float* pp = g_part + (size_t)b * NCHUNK * MD + r4;
    float4 s = make_float4(0.f, 0.f, 0.f, 0.f);
    #pragma unroll 4
    for (int c = 0; c < NCHUNK; ++c) {
        float4 v = *(const float4*)(pp + (size_t)c * MD);
        s.x += v.x; s.y += v.y; s.z += v.z; s.w += v.w;
    }
    *(float4*)(dst + (size_t)b * MD + r4) = s;
}

// ===========================================================================
// launch
// ===========================================================================
extern "C" void kernel_launch(void* const* d_in, const int* in_sizes, int n_in,
                              void* d_out, int out_size) {
    const float* x   = (const float*)d_in[0];
    const float* act = (const float*)d_in[1];
    const float* W   = (const float*)d_in[2];

    float* out       = (float*)d_out;
    float* out_ncv   = out;
    float* out_q     = out + (size_t)BB * MM * DOUTD;
    float* out_route = out_q + (size_t)BB * NIN * MM;

    cudaFuncSetAttribute(votes_tf32_kernel, cudaFuncAttributeMaxDynamicSharedMemorySize, VSMEM);
    cudaFuncSetAttribute(route_iter_kernel, cudaFuncAttributeMaxDynamicSharedMemorySize, ITER_SMEM);

    prep_kernel<<<PREP_BLOCKS, 256>>>(x, W);
    votes_tf32_kernel<<<dim3(MD / BNV, BB / BMV), 256, VSMEM>>>();   // ncv0 fused

    route_iter_kernel<<<dim3(BB, NCHUNK), 256, ITER_SMEM>>>(act, 0, nullptr, nullptr);
    reduce_kernel<<<(BB * MD / 4) / 256, 256>>>(0, nullptr);
    route_iter_kernel<<<dim3(BB, NCHUNK), 256, ITER_SMEM>>>(act, 0, nullptr, nullptr);
    reduce_kernel<<<(BB * MD / 4) / 256, 256>>>(0, nullptr);
    route_iter_kernel<<<dim3(BB, NCHUNK), 256, ITER_SMEM>>>(act, 1, out_q, out_route);
    reduce_kernel<<<(BB * MD / 4) / 256, 256>>>(1, out_ncv);
}